// round 13
// baseline (speedup 1.0000x reference)
#include <cuda_runtime.h>
#include <cuda_bf16.h>
#include <math_constants.h>
#include <stdint.h>

#define KCODES 512
#define DDIM   64
#define QELEMS 4194304
#define NBLK   148
#define NTHR   256
#define THRG   2e-4f          // gap threshold; split-filter err <= ~1e-5

__device__ double   g_partial[NBLK];
__device__ unsigned g_count = 0;
// Packed B-fragments, conflict-free layout: [nb][j][lane], j in {0,1}
__device__ uint4 g_wph[64 * 64];
__device__ uint4 g_wpl[64 * 64];

// ---- smem float offsets ----
#define OFF_SWH   0           // [16384] packed hi fragments (64 KB)
#define OFF_SWL   16384       // [16384] packed lo fragments (64 KB)
#define OFF_SX    32768       // [64][68] f32 exact x
#define OFF_SXH   37120       // [64][72] bf16 hi (2304 f)
#define OFF_SXL   39424       // [64][72] bf16 lo
#define OFF_SB    41728       // [512] exact code norms
#define OFF_SA    42240       // [64] exact row norms
#define OFF_WD1   42304       // [8][64]
#define OFF_WK1   42816       // [8][64] int
#define OFF_WD2   43328       // [8][64]
#define OFF_WIN   43840       // [64] int
#define OFF_FLIST 43904       // [64] int
#define OFF_FCNT  43968       // int (+pad)
#define OFF_SRED  43970       // [256] double (43970*4 % 8 == 0)
#define SMEM_BYTES ((OFF_SRED + 512) * 4)   // 177928 B

// ---------------------------------------------------------------------------
// K1: split w into bf16 hi/lo, pack into MMA B-fragment order.
// Layout: g[nb*64 + j*32 + lane]; j=0 holds ks0,ks1; j=1 holds ks2,ks3.
// ---------------------------------------------------------------------------
__device__ __forceinline__ unsigned bf2u(float a, float b) {
    __nv_bfloat162 h;
    h.x = __float2bfloat16(a);
    h.y = __float2bfloat16(b);
    return *(unsigned*)&h;
}
__global__ void prep_w(const float* __restrict__ w) {
    int t = blockIdx.x * 256 + threadIdx.x;    // 0..2047
    int nb = t >> 5, lane = t & 31;
    int n  = nb * 8 + (lane >> 2);
    int c0 = (lane & 3) * 2;
    unsigned hh[8], ll[8];
    #pragma unroll
    for (int ks = 0; ks < 4; ks++) {
        int kc = ks * 16 + c0;
        #pragma unroll
        for (int p = 0; p < 2; p++) {
            float v0 = w[n * DDIM + kc + p * 8];
            float v1 = w[n * DDIM + kc + p * 8 + 1];
            __nv_bfloat16 h0 = __float2bfloat16(v0);
            __nv_bfloat16 h1 = __float2bfloat16(v1);
            hh[ks * 2 + p] = bf2u(v0, v1);
            ll[ks * 2 + p] = bf2u(__fsub_rn(v0, __bfloat162float(h0)),
                                  __fsub_rn(v1, __bfloat162float(h1)));
        }
    }
    int base = nb * 64 + lane;
    g_wph[base]      = make_uint4(hh[0], hh[1], hh[2], hh[3]);
    g_wph[base + 32] = make_uint4(hh[4], hh[5], hh[6], hh[7]);
    g_wpl[base]      = make_uint4(ll[0], ll[1], ll[2], ll[3]);
    g_wpl[base + 32] = make_uint4(ll[4], ll[5], ll[6], ll[7]);
}

// ---------------------------------------------------------------------------
__device__ __forceinline__ void mma_bf16(float c[4], const unsigned a[4],
                                         unsigned b0, unsigned b1) {
    asm volatile(
        "mma.sync.aligned.m16n8k16.row.col.f32.bf16.bf16.f32 "
        "{%0,%1,%2,%3},{%4,%5,%6,%7},{%8,%9},{%0,%1,%2,%3};"
        : "+f"(c[0]), "+f"(c[1]), "+f"(c[2]), "+f"(c[3])
        : "r"(a[0]), "r"(a[1]), "r"(a[2]), "r"(a[3]), "r"(b0), "r"(b1));
}
__device__ __forceinline__ void upd2(float d, int k, float& d1, int& k1, float& d2) {
    if (d < d1) { d2 = d1; d1 = d; k1 = k; }
    else if (d < d2) d2 = d;
}
__device__ __forceinline__ void mrg(float& d1, int& k1, float& d2, int m) {
    float od1 = __shfl_xor_sync(0xffffffffu, d1, m);
    int   ok1 = __shfl_xor_sync(0xffffffffu, k1, m);
    float od2 = __shfl_xor_sync(0xffffffffu, d2, m);
    if (od1 < d1) { d2 = fminf(d1, od2); d1 = od1; k1 = ok1; }
    else          { d2 = fminf(d2, od1); }
}

// Zero 64 enc rows; enc base only 4B-aligned -> scalar fringes
__device__ __forceinline__ void zero_rows(float* __restrict__ enc,
                                          int row0, int tid) {
    float* p = enc + (size_t)row0 * KCODES;
    const int n = 64 * KCODES;
    uintptr_t a = (uintptr_t)p;
    int head = (int)((((a + 15) & ~(uintptr_t)15) - a) >> 2);
    if (tid < head) p[tid] = 0.0f;
    int n4 = (n - head) >> 2;
    int tail = (n - head) & 3;
    float4* v = (float4*)(p + head);
    float4 z = make_float4(0.f, 0.f, 0.f, 0.f);
    #pragma unroll 4
    for (int i = tid; i < n4; i += NTHR) v[i] = z;
    if (tid >= 4 && tid - 4 < tail) p[head + 4 * n4 + (tid - 4)] = 0.0f;
}

// ---------------------------------------------------------------------------
__global__ void __launch_bounds__(NTHR, 1) vq_main(
    const float* __restrict__ x,
    const float* __restrict__ w,
    float* __restrict__ out,
    float* __restrict__ qout,
    float* __restrict__ enc)
{
    extern __shared__ float sm[];
    const uint4* swh4 = (const uint4*)(sm + OFF_SWH);
    const uint4* swl4 = (const uint4*)(sm + OFF_SWL);
    float* sx  = sm + OFF_SX;
    __nv_bfloat16* sxh = (__nv_bfloat16*)(sm + OFF_SXH);
    __nv_bfloat16* sxl = (__nv_bfloat16*)(sm + OFF_SXL);
    float* sb  = sm + OFF_SB;
    float* sa  = sm + OFF_SA;
    float* wd1 = sm + OFF_WD1;
    int*   wk1 = (int*)(sm + OFF_WK1);
    float* wd2 = sm + OFF_WD2;
    int*   win = (int*)(sm + OFF_WIN);
    int*   flist = (int*)(sm + OFF_FLIST);
    int*   fcnt  = (int*)(sm + OFF_FCNT);
    double* sred = (double*)(sm + OFF_SRED);

    const int tid  = threadIdx.x;
    const int bid  = blockIdx.x;
    const int wid  = tid >> 5;
    const int lane = tid & 31;

    // Stage packed codebook fragment planes into smem once (static data)
    {
        uint4* dh = (uint4*)(sm + OFF_SWH);
        uint4* dl = (uint4*)(sm + OFF_SWL);
        #pragma unroll 4
        for (int i = tid; i < 4096; i += NTHR) {
            dh[i] = g_wph[i];
            dl[i] = g_wpl[i];
        }
    }

    // Exact code norms (reference chain) once per block
    #pragma unroll 1
    for (int k = tid; k < KCODES; k += NTHR) {
        float acc = 0.0f;
        #pragma unroll 8
        for (int d = 0; d < DDIM; d++) {
            float v = w[k * DDIM + d];
            acc = __fadd_rn(acc, __fmul_rn(v, v));
        }
        sb[k] = acc;
    }

    // Tiles: blocks 0-135 get 7, 136-147 get 6  (136*7 + 12*6 = 1024)
    const int cnt = (bid < 136) ? 7 : 6;
    const int t0  = (bid < 136) ? bid * 7 : 952 + (bid - 136) * 6;

    double ls = 0.0;

    #pragma unroll 1
    for (int t = 0; t < cnt; t++) {
        const int row0 = (t0 + t) * 64;
        __syncthreads();   // previous tile fully consumed / staging visible

        if (tid == 0) *fcnt = 0;
        zero_rows(enc, row0, tid);   // drains under compute

        // ---- Stage x tile: fp32 + bf16 hi/lo (bounded unroll) ------------
        #pragma unroll 4
        for (int i = 0; i < 16; i++) {
            int idx = i * NTHR + tid;
            int r = idx & 63, d = idx >> 6;
            int n = row0 + r, b = n >> 10, hw = n & 1023;
            float v = x[(size_t)b * 65536 + hw + (size_t)d * 1024];
            sx[r * 68 + d] = v;
            __nv_bfloat16 h = __float2bfloat16(v);
            sxh[r * 72 + d] = h;
            sxl[r * 72 + d] = __float2bfloat16(__fsub_rn(v, __bfloat162float(h)));
        }
        __syncthreads();

        // Exact row norms (sequential reference chain)
        if (tid < 64) {
            const float* pr = sx + tid * 68;
            float acc = 0.0f;
            #pragma unroll 8
            for (int d = 0; d < DDIM; d++)
                acc = __fadd_rn(acc, __fmul_rn(pr[d], pr[d]));
            sa[tid] = acc;
        }
        __syncthreads();

        // ---- MMA filter with streaming (min1, k1, min2) per row ----------
        #pragma unroll 1
        for (int mt = 0; mt < 4; mt++) {
            const int rr = mt * 16 + (lane >> 2);
            unsigned ah[4][4], al[4][4];
            {
                int c = (lane & 3) * 2;
                #pragma unroll
                for (int ks = 0; ks < 4; ks++) {
                    int kc = ks * 16 + c;
                    ah[ks][0] = *(const unsigned*)(sxh + rr * 72 + kc);
                    ah[ks][1] = *(const unsigned*)(sxh + (rr + 8) * 72 + kc);
                    ah[ks][2] = *(const unsigned*)(sxh + rr * 72 + kc + 8);
                    ah[ks][3] = *(const unsigned*)(sxh + (rr + 8) * 72 + kc + 8);
                    al[ks][0] = *(const unsigned*)(sxl + rr * 72 + kc);
                    al[ks][1] = *(const unsigned*)(sxl + (rr + 8) * 72 + kc);
                    al[ks][2] = *(const unsigned*)(sxl + rr * 72 + kc + 8);
                    al[ks][3] = *(const unsigned*)(sxl + (rr + 8) * 72 + kc + 8);
                }
            }
            float saA = sa[rr], saB = sa[rr + 8];
            float d1a = CUDART_INF_F, d2a = CUDART_INF_F;
            float d1b = CUDART_INF_F, d2b = CUDART_INF_F;
            int   k1a = 0, k1b = 0;

            #pragma unroll 2
            for (int nt = 0; nt < 8; nt++) {
                const int base = (wid * 8 + nt) * 64 + lane;
                uint4 H0 = swh4[base], H1 = swh4[base + 32];
                uint4 L0 = swl4[base], L1 = swl4[base + 32];
                float acc[4] = {0.f, 0.f, 0.f, 0.f};
                mma_bf16(acc, al[0], H0.x, H0.y);
                mma_bf16(acc, ah[0], L0.x, L0.y);
                mma_bf16(acc, ah[0], H0.x, H0.y);
                mma_bf16(acc, al[1], H0.z, H0.w);
                mma_bf16(acc, ah[1], L0.z, L0.w);
                mma_bf16(acc, ah[1], H0.z, H0.w);
                mma_bf16(acc, al[2], H1.x, H1.y);
                mma_bf16(acc, ah[2], L1.x, L1.y);
                mma_bf16(acc, ah[2], H1.x, H1.y);
                mma_bf16(acc, al[3], H1.z, H1.w);
                mma_bf16(acc, ah[3], L1.z, L1.w);
                mma_bf16(acc, ah[3], H1.z, H1.w);

                const int nn = wid * 64 + nt * 8 + (lane & 3) * 2;
                float sb0 = sb[nn], sb1 = sb[nn + 1];
                upd2(saA + sb0 - 2.0f * acc[0], nn,     d1a, k1a, d2a);
                upd2(saA + sb1 - 2.0f * acc[1], nn + 1, d1a, k1a, d2a);
                upd2(saB + sb0 - 2.0f * acc[2], nn,     d1b, k1b, d2b);
                upd2(saB + sb1 - 2.0f * acc[3], nn + 1, d1b, k1b, d2b);
            }
            mrg(d1a, k1a, d2a, 1); mrg(d1a, k1a, d2a, 2);
            mrg(d1b, k1b, d2b, 1); mrg(d1b, k1b, d2b, 2);
            if ((lane & 3) == 0) {
                wd1[wid * 64 + rr] = d1a; wk1[wid * 64 + rr] = k1a;
                wd2[wid * 64 + rr] = d2a;
                wd1[wid * 64 + rr + 8] = d1b; wk1[wid * 64 + rr + 8] = k1b;
                wd2[wid * 64 + rr + 8] = d2b;
            }
        }
        __syncthreads();

        // ---- Per-row merge over 8 warps + gap decision -------------------
        if (tid < 64) {
            float d1 = CUDART_INF_F, d2 = CUDART_INF_F; int k1 = 0;
            #pragma unroll
            for (int ww = 0; ww < 8; ww++) {
                float od1 = wd1[ww * 64 + tid];
                float od2 = wd2[ww * 64 + tid];
                int   ok1 = wk1[ww * 64 + tid];
                if (od1 < d1) { d2 = fminf(d1, od2); d1 = od1; k1 = ok1; }
                else          { d2 = fminf(d2, od1); }
            }
            if (d2 - d1 > THRG) {
                win[tid] = k1;             // provably exact argmin
            } else {
                int idx = atomicAdd(fcnt, 1);
                flist[idx] = tid;          // rare: exact full rescan
            }
        }
        __syncthreads();

        // ---- Warp-parallel exact rescan of flagged rows ------------------
        {
            int nf = *fcnt;
            #pragma unroll 1
            for (int i = wid; i < nf; i += 8) {
                int r = flist[i];
                const float* xr = sx + r * 68;          // broadcast LDS
                float a = sa[r];
                float best = CUDART_INF_F; int bi = 0x7fffffff;
                #pragma unroll 1
                for (int j = 0; j < 16; j++) {
                    int k = lane + 32 * j;
                    const float* wk = w + (size_t)k * DDIM;
                    float m = 0.0f;
                    #pragma unroll 8
                    for (int d = 0; d < DDIM; d++)
                        m = __fmaf_rn(xr[d], wk[d], m);   // reference chain
                    float dd = __fsub_rn(__fadd_rn(a, sb[k]), __fmul_rn(2.0f, m));
                    if (dd < best || (dd == best && k < bi)) { best = dd; bi = k; }
                }
                #pragma unroll
                for (int m2 = 16; m2 > 0; m2 >>= 1) {
                    float od = __shfl_xor_sync(0xffffffffu, best, m2);
                    int   ok = __shfl_xor_sync(0xffffffffu, bi,   m2);
                    if (od < best || (od == best && ok < bi)) { best = od; bi = ok; }
                }
                if (lane == 0) win[r] = bi;
            }
        }
        __syncthreads();

        // ---- Epilogue: q_out (straight-through), one-hot, loss -----------
        #pragma unroll 2
        for (int i = 0; i < 16; i++) {
            int idx = i * NTHR + tid;
            int r = idx & 63, d = idx >> 6;
            int n = row0 + r, b = n >> 10, hw = n & 1023;
            int bi = win[r];
            float xv   = sx[r * 68 + d];
            float diff = __fsub_rn(w[(size_t)bi * DDIM + d], xv);
            qout[(size_t)b * 65536 + hw + (size_t)d * 1024] = __fadd_rn(xv, diff);
            ls += (double)__fmul_rn(diff, diff);
        }
        if (tid < 64)
            enc[(size_t)(row0 + tid) * KCODES + win[tid]] = 1.0f;
    }

    // ---- Deterministic loss reduction -------------------------------------
    __syncthreads();
    sred[tid] = ls;
    __syncthreads();
    for (int s = NTHR / 2; s > 0; s >>= 1) {
        if (tid < s) sred[tid] += sred[tid + s];
        __syncthreads();
    }
    __shared__ int isLast;
    if (tid == 0) {
        g_partial[bid] = sred[0];
        __threadfence();
        unsigned old = atomicAdd(&g_count, 1u);
        isLast = (old == NBLK - 1u) ? 1 : 0;
    }
    __syncthreads();
    if (isLast) {
        sred[tid] = (tid < NBLK) ? g_partial[tid] : 0.0;
        __syncthreads();
        for (int s = NTHR / 2; s > 0; s >>= 1) {
            if (tid < s) sred[tid] += sred[tid + s];
            __syncthreads();
        }
        if (tid == 0) {
            float m = (float)(sred[0] / (double)QELEMS);
            out[0] = __fadd_rn(m, __fmul_rn(0.25f, m));   // z_q + 0.25*z_e
            g_count = 0;                                  // reset for replay
        }
    }
}

// ---------------------------------------------------------------------------
extern "C" void kernel_launch(void* const* d_in, const int* in_sizes, int n_in,
                              void* d_out, int out_size) {
    const float* x = (const float*)d_in[0];   // [64,64,32,32] fp32
    const float* w = (const float*)d_in[1];   // [512,64] fp32
    float* out  = (float*)d_out;
    float* qout = out + 1;                    // [4194304] (4B-aligned only)
    float* enc  = out + 1 + QELEMS;           // [65536*512] (4B-aligned only)

    cudaFuncSetAttribute(vq_main, cudaFuncAttributeMaxDynamicSharedMemorySize,
                         SMEM_BYTES);

    prep_w<<<8, 256>>>(w);
    vq_main<<<NBLK, NTHR, SMEM_BYTES>>>(x, w, out, qout, enc);
}

// round 15
// speedup vs baseline: 3.7544x; 3.7544x over previous
#include <cuda_runtime.h>
#include <math_constants.h>
#include <stdint.h>

#define KCODES 512
#define DDIM   64
#define QELEMS 4194304
#define NBLK   148
#define NTHR   256            // 8 warps; reg budget 64K/256 = 255

__device__ double   g_partial[NBLK];
__device__ unsigned g_count = 0;

// ---- smem float offsets ----
#define OFF_SW    0            // [512][64] codebook
#define OFF_SB    32768        // [512] code norms
#define OFF_SXT   33280        // [128][69] staged x (pair of rowsets)
#define OFF_MBB   42112        // [4][128] partial best dist
#define OFF_MBI   42624        // [4][128] partial best idx
#define OFF_SRED  43136        // [256] double (43136*4 % 8 == 0)
#define SMEM_BYTES ((OFF_SRED + 512) * 4)   // 174592 B

// ---------------------------------------------------------------------------
// Zero this block's encoding rows; enc base is only 4B-aligned
// (d_out+4+4*QELEMS) -> scalar fringes around a float4 interior.
// ---------------------------------------------------------------------------
__device__ __forceinline__ void zero_rows(float* __restrict__ enc,
                                          int row0, int nrows, int tid) {
    float* p = enc + (size_t)row0 * KCODES;
    int n = nrows * KCODES;
    uintptr_t a = (uintptr_t)p;
    int head = (int)((((a + 15) & ~(uintptr_t)15) - a) >> 2);   // 0..3
    if (tid < head) p[tid] = 0.0f;
    int n4 = (n - head) >> 2;
    int tail = (n - head) & 3;
    float4* v = (float4*)(p + head);
    float4 z = make_float4(0.f, 0.f, 0.f, 0.f);
    #pragma unroll 4
    for (int i = tid; i < n4; i += NTHR) v[i] = z;
    if (tid >= 4 && tid - 4 < tail) p[head + 4 * n4 + (tid - 4)] = 0.0f;
}

// ---------------------------------------------------------------------------
// Fused kernel (R7 core + cooperative x staging).
// Job = 1 warp x 64 rows (2/lane) x 128 codes (one k-quarter).
// Iteration i: rowsets 2i, 2i+1 staged in smem; warp w -> rowset (w>>2),
// quarter (w&3). Every SMSP gets 7 (or 6) jobs total -> balanced.
// ---------------------------------------------------------------------------
__global__ void __launch_bounds__(NTHR, 1) vq_fused(
    const float* __restrict__ x,
    const float* __restrict__ w,
    float* __restrict__ out,       // out[0] = loss
    float* __restrict__ qout,
    float* __restrict__ enc)
{
    extern __shared__ float sm[];
    float*  sw   = sm + OFF_SW;                // [512*64]
    float*  sb   = sm + OFF_SB;                // [512]
    float*  sxt  = sm + OFF_SXT;               // [128][69]
    float*  mbb  = sm + OFF_MBB;               // [4][128]
    int*    mbi  = (int*)(sm + OFF_MBI);       // [4][128]
    double* sred = (double*)(sm + OFF_SRED);   // [256]

    const int tid  = threadIdx.x;
    const int bid  = blockIdx.x;
    const int wid  = tid >> 5;
    const int lane = tid & 31;

    // Block -> contiguous 64-row rowsets: 136 blocks x 7, 12 blocks x 6
    const int cnt   = (bid < 136) ? 7 : 6;
    const int rs0   = (bid < 136) ? bid * 7 : 952 + (bid - 136) * 6;
    const int niter = (cnt + 1) >> 1;          // 4 or 3

    // Stage codebook (coalesced float4; w is harness-aligned)
    {
        const float4* w4 = (const float4*)w;
        float4*       s4 = (float4*)sw;
        #pragma unroll 4
        for (int i = tid; i < 8192; i += NTHR) s4[i] = w4[i];
    }

    // Zero-fill exactly this block's enc rows (drains under the FFMA loop)
    zero_rows(enc, rs0 * 64, cnt * 64, tid);
    __syncthreads();

    // Codebook norms — identical rounding chain to reference
    #pragma unroll 1
    for (int k = tid; k < KCODES; k += NTHR) {
        float acc = 0.0f;
        #pragma unroll 8
        for (int d = 0; d < DDIM; d++) {
            float v = sw[k * DDIM + d];
            acc = __fadd_rn(acc, __fmul_rn(v, v));
        }
        sb[k] = acc;
    }

    double ls = 0.0;

    #pragma unroll 1
    for (int i = 0; i < niter; i++) {
        const int nrs   = ((cnt - 2 * i) >= 2) ? 2 : 1;   // rowsets this iter
        const int row0i = (rs0 + 2 * i) * 64;             // first global row
        const int nrows = nrs * 64;

        __syncthreads();   // previous iter's merge done reading sxt

        // ---- Cooperative x staging (coalesced LDG, conflict-free STS) ----
        {
            const int items = nrows * DDIM;               // 8192 or 4096
            #pragma unroll 4
            for (int idx = tid; idx < items; idx += NTHR) {
                int r = idx % nrows, d = idx / nrows;     // nrows = 128/64
                int n = row0i + r, b = n >> 10, hw = n & 1023;
                sxt[r * 69 + d] = x[(size_t)b * 65536 + hw + (size_t)d * 1024];
            }
        }
        __syncthreads();

        // ---- Quarter jobs: warp w -> rowset w>>2, quarter w&3 ------------
        const int lrs = wid >> 2;
        const int q   = wid & 3;
        if (lrs < nrs) {
            const int r0 = lrs * 64 + lane;      // local rows
            const int r1 = r0 + 32;

            float xr0[DDIM], xr1[DDIM];
            #pragma unroll 8
            for (int d = 0; d < DDIM; d++) xr0[d] = sxt[r0 * 69 + d];
            #pragma unroll 8
            for (int d = 0; d < DDIM; d++) xr1[d] = sxt[r1 * 69 + d];

            // a = sum(x*x): fp32 sequential, rounded mul then add (no FMA)
            float a0 = 0.0f, a1 = 0.0f;
            #pragma unroll
            for (int d = 0; d < DDIM; d++) {
                a0 = __fadd_rn(a0, __fmul_rn(xr0[d], xr0[d]));
                a1 = __fadd_rn(a1, __fmul_rn(xr1[d], xr1[d]));
            }

            float best0 = CUDART_INF_F, best1 = CUDART_INF_F;
            int   bi0 = 0, bi1 = 0;
            const int kbase = q << 7;            // 128 codes per quarter

            #pragma unroll 1
            for (int kk = 0; kk < 128; kk += 2) {
                const int k0 = kbase + kk;
                const float4* w0 = (const float4*)(sw + (k0 << 6));
                float ma0 = 0.0f, mb0 = 0.0f, ma1 = 0.0f, mb1 = 0.0f;
                #pragma unroll
                for (int j = 0; j < 16; j++) {
                    float4 u = w0[j];        // code k0
                    float4 v = w0[j + 16];   // code k0+1
                    ma0 = __fmaf_rn(xr0[4*j+0], u.x, ma0);
                    ma0 = __fmaf_rn(xr0[4*j+1], u.y, ma0);
                    ma0 = __fmaf_rn(xr0[4*j+2], u.z, ma0);
                    ma0 = __fmaf_rn(xr0[4*j+3], u.w, ma0);
                    mb0 = __fmaf_rn(xr0[4*j+0], v.x, mb0);
                    mb0 = __fmaf_rn(xr0[4*j+1], v.y, mb0);
                    mb0 = __fmaf_rn(xr0[4*j+2], v.z, mb0);
                    mb0 = __fmaf_rn(xr0[4*j+3], v.w, mb0);
                    ma1 = __fmaf_rn(xr1[4*j+0], u.x, ma1);
                    ma1 = __fmaf_rn(xr1[4*j+1], u.y, ma1);
                    ma1 = __fmaf_rn(xr1[4*j+2], u.z, ma1);
                    ma1 = __fmaf_rn(xr1[4*j+3], u.w, ma1);
                    mb1 = __fmaf_rn(xr1[4*j+0], v.x, mb1);
                    mb1 = __fmaf_rn(xr1[4*j+1], v.y, mb1);
                    mb1 = __fmaf_rn(xr1[4*j+2], v.z, mb1);
                    mb1 = __fmaf_rn(xr1[4*j+3], v.w, mb1);
                }
                float b0 = sb[k0], b1 = sb[k0 + 1];
                // d = fl( fl(a + b) - fl(2*m) ) — exact reference rounding
                float d00 = __fsub_rn(__fadd_rn(a0, b0), __fmul_rn(2.0f, ma0));
                float d01 = __fsub_rn(__fadd_rn(a0, b1), __fmul_rn(2.0f, mb0));
                float d10 = __fsub_rn(__fadd_rn(a1, b0), __fmul_rn(2.0f, ma1));
                float d11 = __fsub_rn(__fadd_rn(a1, b1), __fmul_rn(2.0f, mb1));
                if (d00 < best0) { best0 = d00; bi0 = k0; }
                if (d01 < best0) { best0 = d01; bi0 = k0 + 1; }
                if (d10 < best1) { best1 = d10; bi1 = k0; }
                if (d11 < best1) { best1 = d11; bi1 = k0 + 1; }
            }

            // Store partials; [q][localrow] -> consecutive lanes, no conflicts
            mbb[q * 128 + r0] = best0;
            mbb[q * 128 + r1] = best1;
            mbi[q * 128 + r0] = bi0;
            mbi[q * 128 + r1] = bi1;
        }
        __syncthreads();

        // ---- Merge quarters + outputs (x still staged in sxt) ------------
        if (tid < nrows) {
            const int rl = tid;
            // Ascending-q merge with strict < == global first-index argmin
            float best = CUDART_INF_F; int bi = 0;
            #pragma unroll
            for (int qq = 0; qq < 4; qq++) {
                float d = mbb[qq * 128 + rl];
                int   k = mbi[qq * 128 + rl];
                if (d < best) { best = d; bi = k; }
            }
            const int n = row0i + rl;
            const int b = n >> 10, hw = n & 1023;
            float*       qp = qout + (size_t)b * 65536 + hw;
            const float* wq = sw + bi * DDIM;
            const float* xr = sxt + rl * 69;
            #pragma unroll 8
            for (int d = 0; d < DDIM; d++) {
                float xv   = xr[d];
                float diff = __fsub_rn(wq[d], xv);
                qp[(size_t)d * 1024] = __fadd_rn(xv, diff);   // straight-through
                ls += (double)__fmul_rn(diff, diff);
            }
            enc[(size_t)n * KCODES + bi] = 1.0f;
        }
    }

    // ---- Deterministic block-level loss reduction (fixed tree) -------------
    __syncthreads();
    sred[tid] = ls;
    __syncthreads();
    for (int s = NTHR / 2; s > 0; s >>= 1) {
        if (tid < s) sred[tid] += sred[tid + s];
        __syncthreads();
    }

    // Last-block final reduce (fence+atomic; deterministic fixed-order sum)
    __shared__ int isLast;
    if (tid == 0) {
        g_partial[bid] = sred[0];
        __threadfence();
        unsigned old = atomicAdd(&g_count, 1u);
        isLast = (old == NBLK - 1u) ? 1 : 0;
    }
    __syncthreads();
    if (isLast) {
        sred[tid] = (tid < NBLK) ? g_partial[tid] : 0.0;
        __syncthreads();
        for (int s = NTHR / 2; s > 0; s >>= 1) {
            if (tid < s) sred[tid] += sred[tid + s];
            __syncthreads();
        }
        if (tid == 0) {
            float m = (float)(sred[0] / (double)QELEMS);
            out[0] = __fadd_rn(m, __fmul_rn(0.25f, m));  // z_q + 0.25*z_e
            g_count = 0;                                 // reset for replay
        }
    }
}

// ---------------------------------------------------------------------------
extern "C" void kernel_launch(void* const* d_in, const int* in_sizes, int n_in,
                              void* d_out, int out_size) {
    const float* x = (const float*)d_in[0];   // [64,64,32,32] fp32
    const float* w = (const float*)d_in[1];   // [512,64] fp32
    float* out  = (float*)d_out;
    float* qout = out + 1;                    // [4194304] (4B-aligned only)
    float* enc  = out + 1 + QELEMS;           // [65536*512] (4B-aligned only)

    cudaFuncSetAttribute(vq_fused, cudaFuncAttributeMaxDynamicSharedMemorySize,
                         SMEM_BYTES);

    vq_fused<<<NBLK, NTHR, SMEM_BYTES>>>(x, w, out, qout, enc);
}

// round 16
// speedup vs baseline: 4.2967x; 1.1445x over previous
#include <cuda_runtime.h>
#include <math_constants.h>
#include <stdint.h>

#define KCODES 512
#define DDIM   64
#define QELEMS 4194304
#define NBLK   148
#define NTHR   384            // 12 warps = 3 per SMSP
#define MAXROWS 448           // max rows per block (7 rowsets x 64)

__device__ double   g_partial[NBLK];
__device__ unsigned g_count = 0;

// smem floats: sw 32768 | sb 512 | mbb 4*448 | mbi 4*448 | sred 384 doubles
#define OFF_SW   0
#define OFF_SB   32768
#define OFF_MBB  33280
#define OFF_MBI  35072
#define OFF_SRED 36864        // 36864*4 % 8 == 0
#define SMEM_BYTES (OFF_SRED * 4 + NTHR * 8)   // 150528 B

// ---------------------------------------------------------------------------
// Zero this block's encoding rows; enc base is only 4B-aligned
// (d_out+4+4*QELEMS) -> scalar fringes around a float4 interior.
// ---------------------------------------------------------------------------
__device__ __forceinline__ void zero_rows(float* __restrict__ enc,
                                          int row0, int nrows, int tid) {
    float* p = enc + (size_t)row0 * KCODES;
    int n = nrows * KCODES;
    uintptr_t a = (uintptr_t)p;
    int head = (int)((((a + 15) & ~(uintptr_t)15) - a) >> 2);   // 0..3
    if (tid < head) p[tid] = 0.0f;
    int n4 = (n - head) >> 2;
    int tail = (n - head) & 3;
    float4* v = (float4*)(p + head);
    float4 z = make_float4(0.f, 0.f, 0.f, 0.f);
    #pragma unroll 4
    for (int i = tid; i < n4; i += NTHR) v[i] = z;
    if (tid >= 4 && tid - 4 < tail) p[head + 4 * n4 + (tid - 4)] = 0.0f;
}

// ---------------------------------------------------------------------------
// R7 core with 12 warps. Job = 1 warp x 64 rows (2/lane) x 128 codes.
// Warp w takes jobs jj = w + 12*i -> per-SMSP job totals stay exactly 7 (6).
// All codebook LDS are warp-broadcast (whole warp on one code).
// ---------------------------------------------------------------------------
__global__ void __launch_bounds__(NTHR, 1) vq_fused(
    const float* __restrict__ x,
    const float* __restrict__ w,
    float* __restrict__ out,       // out[0] = loss
    float* __restrict__ qout,
    float* __restrict__ enc)
{
    extern __shared__ float sm[];
    float*  sw   = sm + OFF_SW;                // [512*64]
    float*  sb   = sm + OFF_SB;                // [512]
    float*  mbb  = sm + OFF_MBB;               // [4][448]
    int*    mbi  = (int*)(sm + OFF_MBI);       // [4][448]
    double* sred = (double*)(sm + OFF_SRED);   // [384]

    const int tid  = threadIdx.x;
    const int bid  = blockIdx.x;
    const int wid  = tid >> 5;
    const int lane = tid & 31;

    // Block -> contiguous run of 64-row rowsets: 136 blocks x 7, 12 blocks x 6
    const int cnt   = (bid < 136) ? 7 : 6;
    const int rs0   = (bid < 136) ? bid * 7 : 952 + (bid - 136) * 6;
    const int row0  = rs0 * 64;
    const int nrows = cnt * 64;
    const int njobs = cnt * 4;                 // 28 or 24

    // Stage codebook (coalesced float4; w is harness-aligned)
    {
        const float4* w4 = (const float4*)w;
        float4*       s4 = (float4*)sw;
        #pragma unroll 4
        for (int i = tid; i < 8192; i += NTHR) s4[i] = w4[i];
    }

    // Zero-fill exactly this block's enc rows (drains under the FFMA loop)
    zero_rows(enc, row0, nrows, tid);

    __syncthreads();

    // Codebook norms — identical rounding chain to reference
    #pragma unroll 1
    for (int k = tid; k < KCODES; k += NTHR) {
        float acc = 0.0f;
        #pragma unroll 8
        for (int d = 0; d < DDIM; d++) {
            float v = sw[k * DDIM + d];
            acc = __fadd_rn(acc, __fmul_rn(v, v));
        }
        sb[k] = acc;
    }
    __syncthreads();

    // ---------------- Main phase: quarter-jobs ----------------------------
    // Warp w handles jobs jj = w, w+12, w+24 (< njobs).
    #pragma unroll 1
    for (int i = 0; i < 3; i++) {
        int jj = wid + 12 * i;
        if (jj >= njobs) break;
        const int rsl = jj >> 2;            // local rowset 0..cnt-1
        const int q   = jj & 3;             // code quarter 0..3
        const int n0 = row0 + rsl * 64 + lane;
        const int n1 = n0 + 32;

        // x layout [B=64, D=64, H=32, W=32]: row n -> gather stride 1024
        float xr0[DDIM], xr1[DDIM];
        {
            int b = n0 >> 10, hw = n0 & 1023;
            const float* p = x + (size_t)b * 65536 + hw;
            #pragma unroll
            for (int d = 0; d < DDIM; d++) xr0[d] = p[d * 1024];
        }
        {
            int b = n1 >> 10, hw = n1 & 1023;
            const float* p = x + (size_t)b * 65536 + hw;
            #pragma unroll
            for (int d = 0; d < DDIM; d++) xr1[d] = p[d * 1024];
        }

        // a = sum(x*x): fp32 sequential, rounded mul then add (no FMA)
        float a0 = 0.0f, a1 = 0.0f;
        #pragma unroll
        for (int d = 0; d < DDIM; d++) {
            a0 = __fadd_rn(a0, __fmul_rn(xr0[d], xr0[d]));
            a1 = __fadd_rn(a1, __fmul_rn(xr1[d], xr1[d]));
        }

        float best0 = CUDART_INF_F, best1 = CUDART_INF_F;
        int   bi0 = 0, bi1 = 0;
        const int kbase = q << 7;           // 128 codes per quarter

        #pragma unroll 1
        for (int kk = 0; kk < 128; kk += 2) {
            const int k0 = kbase + kk;
            const float4* w0 = (const float4*)(sw + (k0 << 6));
            float ma0 = 0.0f, mb0 = 0.0f, ma1 = 0.0f, mb1 = 0.0f;
            #pragma unroll
            for (int j = 0; j < 16; j++) {
                float4 u = w0[j];        // code k0
                float4 v = w0[j + 16];   // code k0+1
                ma0 = __fmaf_rn(xr0[4*j+0], u.x, ma0);
                ma0 = __fmaf_rn(xr0[4*j+1], u.y, ma0);
                ma0 = __fmaf_rn(xr0[4*j+2], u.z, ma0);
                ma0 = __fmaf_rn(xr0[4*j+3], u.w, ma0);
                mb0 = __fmaf_rn(xr0[4*j+0], v.x, mb0);
                mb0 = __fmaf_rn(xr0[4*j+1], v.y, mb0);
                mb0 = __fmaf_rn(xr0[4*j+2], v.z, mb0);
                mb0 = __fmaf_rn(xr0[4*j+3], v.w, mb0);
                ma1 = __fmaf_rn(xr1[4*j+0], u.x, ma1);
                ma1 = __fmaf_rn(xr1[4*j+1], u.y, ma1);
                ma1 = __fmaf_rn(xr1[4*j+2], u.z, ma1);
                ma1 = __fmaf_rn(xr1[4*j+3], u.w, ma1);
                mb1 = __fmaf_rn(xr1[4*j+0], v.x, mb1);
                mb1 = __fmaf_rn(xr1[4*j+1], v.y, mb1);
                mb1 = __fmaf_rn(xr1[4*j+2], v.z, mb1);
                mb1 = __fmaf_rn(xr1[4*j+3], v.w, mb1);
            }
            float b0 = sb[k0], b1 = sb[k0 + 1];
            // d = fl( fl(a + b) - fl(2*m) ) — exact reference rounding
            float d00 = __fsub_rn(__fadd_rn(a0, b0), __fmul_rn(2.0f, ma0));
            float d01 = __fsub_rn(__fadd_rn(a0, b1), __fmul_rn(2.0f, mb0));
            float d10 = __fsub_rn(__fadd_rn(a1, b0), __fmul_rn(2.0f, ma1));
            float d11 = __fsub_rn(__fadd_rn(a1, b1), __fmul_rn(2.0f, mb1));
            if (d00 < best0) { best0 = d00; bi0 = k0; }
            if (d01 < best0) { best0 = d01; bi0 = k0 + 1; }
            if (d10 < best1) { best1 = d10; bi1 = k0; }
            if (d11 < best1) { best1 = d11; bi1 = k0 + 1; }
        }

        // Store partials; [q][row] layout -> consecutive lanes, no conflicts
        int r0 = rsl * 64 + lane;
        mbb[q * MAXROWS + r0]      = best0;
        mbb[q * MAXROWS + r0 + 32] = best1;
        mbi[q * MAXROWS + r0]      = bi0;
        mbi[q * MAXROWS + r0 + 32] = bi1;
    }
    __syncthreads();

    // ---------------- Epilogue: merge quarters + outputs -------------------
    double ls = 0.0;
    #pragma unroll 1
    for (int rl = tid; rl < nrows; rl += NTHR) {
        // Ascending-q merge with strict < == global first-index argmin
        float best = CUDART_INF_F; int bi = 0;
        #pragma unroll
        for (int q = 0; q < 4; q++) {
            float d = mbb[q * MAXROWS + rl];
            int   k = mbi[q * MAXROWS + rl];
            if (d < best) { best = d; bi = k; }
        }
        const int n = row0 + rl;
        const int b = n >> 10, hw = n & 1023;
        const float* p  = x    + (size_t)b * 65536 + hw;
        float*       qp = qout + (size_t)b * 65536 + hw;
        const float* wq = sw + bi * DDIM;
        #pragma unroll 8
        for (int d = 0; d < DDIM; d++) {
            float xv   = p[d * 1024];
            float diff = __fsub_rn(wq[d], xv);
            qp[d * 1024] = __fadd_rn(xv, diff);     // straight-through
            ls += (double)__fmul_rn(diff, diff);
        }
        enc[(size_t)n * KCODES + bi] = 1.0f;
    }

    // Deterministic block-level loss reduction (fixed tree, 384 -> 256 -> 1)
    sred[tid] = ls;
    __syncthreads();
    if (tid < 128) sred[tid] += sred[tid + 256];
    __syncthreads();
    for (int s = 128; s > 0; s >>= 1) {
        if (tid < s) sred[tid] += sred[tid + s];
        __syncthreads();
    }

    // Last-block final reduce (fence+atomic; deterministic fixed-order sum)
    __shared__ int isLast;
    if (tid == 0) {
        g_partial[bid] = sred[0];
        __threadfence();
        unsigned old = atomicAdd(&g_count, 1u);
        isLast = (old == NBLK - 1u) ? 1 : 0;
    }
    __syncthreads();
    if (isLast) {
        if (tid < 256) sred[tid] = (tid < NBLK) ? g_partial[tid] : 0.0;
        __syncthreads();
        for (int s = 128; s > 0; s >>= 1) {
            if (tid < s) sred[tid] += sred[tid + s];
            __syncthreads();
        }
        if (tid == 0) {
            float m = (float)(sred[0] / (double)QELEMS);
            out[0] = __fadd_rn(m, __fmul_rn(0.25f, m));  // z_q + 0.25*z_e
            g_count = 0;                                 // reset for replay
        }
    }
}

// ---------------------------------------------------------------------------
extern "C" void kernel_launch(void* const* d_in, const int* in_sizes, int n_in,
                              void* d_out, int out_size) {
    const float* x = (const float*)d_in[0];   // [64,64,32,32] fp32
    const float* w = (const float*)d_in[1];   // [512,64] fp32
    float* out  = (float*)d_out;
    float* qout = out + 1;                    // [4194304] (4B-aligned only)
    float* enc  = out + 1 + QELEMS;           // [65536*512] (4B-aligned only)

    cudaFuncSetAttribute(vq_fused, cudaFuncAttributeMaxDynamicSharedMemorySize,
                         SMEM_BYTES);

    vq_fused<<<NBLK, NTHR, SMEM_BYTES>>>(x, w, out, qout, enc);
}